// round 10
// baseline (speedup 1.0000x reference)
#include <cuda_runtime.h>
#include <cuda_bf16.h>
#include <cstdint>

// Problem constants
#define BB 2048
#define NN 128
#define DD 512
#define EE 64
#define ROWS (BB*NN)            // 262144
#define EPS 1e-6f
#define CAPACITY 2048.0f

#define TILE_M 128
#define THREADS1 416            // 13 warps: 8 convert, 4 x-stage, 1 ctrl (B + MMA)

// ---- tcgen05 path tiling ----
#define KC 64                   // K per chunk (64 bf16 = 128B rows, SW128)
#define NCH (DD/KC)             // 8 chunks
#define B_TILE_B (EE*128)       // 8192 per term
#define B_STAGE_B (3*B_TILE_B)  // 24576 (single stage)
#define XS_TILE_B 16384         // one khalf tile: 128 rows x 128B
#define XS_STAGE_B (2*XS_TILE_B)
#define SMEM_TC (2048 + B_STAGE_B + 2*XS_STAGE_B)   // ~92KB

// TMEM columns: D=0..63, A ring at 64 (stage*96, term*32) -> alloc 256
#define TM_D 0
#define TM_A 64
#define TMEM_COLS 256

// idesc: dtype=F32, atype=BF16, btype=BF16, N=64, M=128, K-major both
#define IDESC ((1u<<4)|(1u<<7)|(1u<<10)|((EE/8)<<17)|((TILE_M/16)<<24))

// Scratch (device globals; no allocation allowed)
__device__ float g_p0[ROWS];
__device__ int   g_idx[ROWS];
__device__ float g_masked[BB*EE];
__device__ float g_denom[EE];
__device__ int   g_load[EE];
// chunk-major pre-swizzled B image: [NCH][3 terms][64 rows x 128B swizzled]
__device__ __align__(128) char g_wimg[NCH * 3 * B_TILE_B];

#define HAS_TCGEN05 (defined(__CUDA_ARCH_FEAT_SM103_ALL) || defined(__CUDA_ARCH_FEAT_SM100_ALL) || defined(__CUDA_ARCH_FEAT_SM101_ALL))

// ---------------- generic helpers ----------------
__device__ __forceinline__ uint32_t sw128(uint32_t o) { return o ^ ((o >> 3) & 0x70); }

__device__ __forceinline__ uint32_t pack_bf2(__nv_bfloat16 a, __nv_bfloat16 b) {
    __nv_bfloat162 t = __halves2bfloat162(a, b);
    return *reinterpret_cast<uint32_t*>(&t);
}

#if HAS_TCGEN05
// ---------------- tcgen05 / TMA PTX helpers (arch-specific target only) ----------------
__device__ __forceinline__ uint32_t smem_u32(const void* p) {
    uint32_t a;
    asm("{ .reg .u64 t; cvta.to.shared.u64 t, %1; cvt.u32.u64 %0, t; }"
        : "=r"(a) : "l"(p));
    return a;
}
__device__ __forceinline__ uint32_t elect1() {
    uint32_t r;
    asm volatile("{\n\t.reg .pred p;\n\telect.sync _|p, 0xFFFFFFFF;\n\t"
                 "selp.b32 %0, 1, 0, p;\n\t}" : "=r"(r));
    return r;
}
__device__ __forceinline__ uint64_t make_desc_sw128(uint32_t addr) {
    const uint64_t base = (2ull << 61) | (1ull << 46) | (64ull << 32) | (1ull << 16);
    return base | ((uint64_t)(addr >> 4) & 0x3FFF);
}
// TS-mode MMA: A in TMEM, B via SMEM descriptor
__device__ __forceinline__ void mma_ts_f16(uint32_t d, uint32_t a, uint64_t b,
                                           uint32_t idesc, uint32_t en) {
    asm volatile(
        "{\n\t.reg .pred p;\n\tsetp.ne.u32 p, %4, 0;\n\t"
        "tcgen05.mma.cta_group::1.kind::f16 [%0], [%1], %2, %3, {%5,%5,%5,%5}, p;\n\t}"
        :: "r"(d), "r"(a), "l"(b), "r"(idesc), "r"(en), "r"(0u) : "memory");
}
__device__ __forceinline__ void mbar_init(uint32_t a, uint32_t cnt) {
    asm volatile("mbarrier.init.shared.b64 [%0], %1;" :: "r"(a), "r"(cnt) : "memory");
}
__device__ __forceinline__ void mbar_arrive(uint32_t a) {
    asm volatile("mbarrier.arrive.release.cta.shared.b64 _, [%0];" :: "r"(a) : "memory");
}
__device__ __forceinline__ void arrive_expect_tx(uint32_t a, uint32_t bytes) {
    asm volatile("mbarrier.arrive.expect_tx.shared.b64 _, [%0], %1;"
                 :: "r"(a), "r"(bytes) : "memory");
}
__device__ __forceinline__ void bulk_g2s(uint32_t dst, const void* src,
                                         uint32_t bytes, uint32_t mbar) {
    asm volatile("cp.async.bulk.shared::cta.global.mbarrier::complete_tx::bytes "
                 "[%0], [%1], %2, [%3];"
                 :: "r"(dst), "l"(src), "r"(bytes), "r"(mbar) : "memory");
}
__device__ __forceinline__ void mbar_wait(uint32_t a, uint32_t parity) {
    uint32_t done;
    asm volatile("{\n\t.reg .pred p;\n\t"
        "mbarrier.try_wait.parity.acquire.cta.shared::cta.b64 p, [%1], %2;\n\t"
        "selp.b32 %0, 1, 0, p;\n\t}" : "=r"(done) : "r"(a), "r"(parity) : "memory");
    while (!done) {
        asm volatile("{\n\t.reg .pred p;\n\t"
            "mbarrier.try_wait.parity.acquire.cta.shared::cta.b64 p, [%1], %2, 0x989680;\n\t"
            "selp.b32 %0, 1, 0, p;\n\t}" : "=r"(done) : "r"(a), "r"(parity) : "memory");
    }
}
__device__ __forceinline__ void t5_commit(uint32_t mb) {
    asm volatile("tcgen05.commit.cta_group::1.mbarrier::arrive::one.shared::cluster.b64 [%0];"
                 :: "r"(mb) : "memory");
}
#define T5_ALLOC(smaddr, n) \
    asm volatile("tcgen05.alloc.cta_group::1.sync.aligned.shared::cta.b32 [%0], %1;" \
                 :: "r"(smaddr), "r"((uint32_t)(n)) : "memory")
#define T5_RELINQ() \
    asm volatile("tcgen05.relinquish_alloc_permit.cta_group::1.sync.aligned;")
#define T5_DEALLOC(t, n) \
    asm volatile("tcgen05.dealloc.cta_group::1.sync.aligned.b32 %0, %1;" :: "r"(t), "r"((uint32_t)(n)))
#define T5_FENCE_AFTER()  asm volatile("tcgen05.fence::after_thread_sync;" ::: "memory")
#define T5_FENCE_BEFORE() asm volatile("tcgen05.fence::before_thread_sync;" ::: "memory")
#define T5_WAIT_LD()      asm volatile("tcgen05.wait::ld.sync.aligned;" ::: "memory")
#define T5_WAIT_ST()      asm volatile("tcgen05.wait::st.sync.aligned;" ::: "memory")

#define STTM8(addr, r) \
    asm volatile("tcgen05.st.sync.aligned.32x32b.x8.b32 [%0], " \
        "{%1,%2,%3,%4,%5,%6,%7,%8};" \
        :: "r"(addr), "r"((r)[0]), "r"((r)[1]), "r"((r)[2]), "r"((r)[3]), \
           "r"((r)[4]), "r"((r)[5]), "r"((r)[6]), "r"((r)[7]) : "memory")

#define LDTM32(r, addr) \
    asm volatile( \
        "tcgen05.ld.sync.aligned.32x32b.x32.b32 " \
        "{%0, %1, %2, %3, %4, %5, %6, %7, " \
        " %8, %9, %10, %11, %12, %13, %14, %15, " \
        " %16, %17, %18, %19, %20, %21, %22, %23, " \
        " %24, %25, %26, %27, %28, %29, %30, %31}, [%32];" \
        : "=r"((r)[0]),  "=r"((r)[1]),  "=r"((r)[2]),  "=r"((r)[3]), \
          "=r"((r)[4]),  "=r"((r)[5]),  "=r"((r)[6]),  "=r"((r)[7]), \
          "=r"((r)[8]),  "=r"((r)[9]),  "=r"((r)[10]), "=r"((r)[11]), \
          "=r"((r)[12]), "=r"((r)[13]), "=r"((r)[14]), "=r"((r)[15]), \
          "=r"((r)[16]), "=r"((r)[17]), "=r"((r)[18]), "=r"((r)[19]), \
          "=r"((r)[20]), "=r"((r)[21]), "=r"((r)[22]), "=r"((r)[23]), \
          "=r"((r)[24]), "=r"((r)[25]), "=r"((r)[26]), "=r"((r)[27]), \
          "=r"((r)[28]), "=r"((r)[29]), "=r"((r)[30]), "=r"((r)[31]) \
        : "r"(addr))
#endif  // HAS_TCGEN05

// ---------------- Kernel 0: build pre-swizzled chunk-major W images ----------------
__global__ void k0h(const float* __restrict__ w) {
    int i = blockIdx.x * blockDim.x + threadIdx.x;      // 0..4095
    int c = i >> 9, e = (i >> 3) & 63, k16 = i & 7;
    const float4* src = reinterpret_cast<const float4*>(w + (size_t)e * DD + c * KC + k16 * 8);
    float4 a = src[0], b = src[1];
    uint32_t o[4];
    o[0] = pack_bf2(__float2bfloat16(a.x), __float2bfloat16(a.y));
    o[1] = pack_bf2(__float2bfloat16(a.z), __float2bfloat16(a.w));
    o[2] = pack_bf2(__float2bfloat16(b.x), __float2bfloat16(b.y));
    o[3] = pack_bf2(__float2bfloat16(b.z), __float2bfloat16(b.w));
    uint32_t off = c * B_STAGE_B + 0 * B_TILE_B + sw128((uint32_t)e * 128 + k16 * 16);
    *reinterpret_cast<uint4*>(g_wimg + off) = make_uint4(o[0], o[1], o[2], o[3]);
}
__device__ __forceinline__ float bf_res1(float v) {
    return v - __bfloat162float(__float2bfloat16(v));
}
__global__ void k0m(const float* __restrict__ w) {
    int i = blockIdx.x * blockDim.x + threadIdx.x;
    int c = i >> 9, e = (i >> 3) & 63, k16 = i & 7;
    const float4* src = reinterpret_cast<const float4*>(w + (size_t)e * DD + c * KC + k16 * 8);
    float4 a = src[0], b = src[1];
    float f[8] = {a.x, a.y, a.z, a.w, b.x, b.y, b.z, b.w};
    uint32_t o[4];
#pragma unroll
    for (int q = 0; q < 4; q++)
        o[q] = pack_bf2(__float2bfloat16(bf_res1(f[q*2])), __float2bfloat16(bf_res1(f[q*2+1])));
    uint32_t off = c * B_STAGE_B + 1 * B_TILE_B + sw128((uint32_t)e * 128 + k16 * 16);
    *reinterpret_cast<uint4*>(g_wimg + off) = make_uint4(o[0], o[1], o[2], o[3]);
}
__global__ void k0l(const float* __restrict__ w) {
    int i = blockIdx.x * blockDim.x + threadIdx.x;
    int c = i >> 9, e = (i >> 3) & 63, k16 = i & 7;
    const float4* src = reinterpret_cast<const float4*>(w + (size_t)e * DD + c * KC + k16 * 8);
    float4 a = src[0], b = src[1];
    float f[8] = {a.x, a.y, a.z, a.w, b.x, b.y, b.z, b.w};
    uint32_t o[4];
#pragma unroll
    for (int q = 0; q < 4; q++) {
        float r0 = bf_res1(f[q*2]),   l0 = bf_res1(r0);
        float r1 = bf_res1(f[q*2+1]), l1 = bf_res1(r1);
        o[q] = pack_bf2(__float2bfloat16(l0), __float2bfloat16(l1));
    }
    uint32_t off = c * B_STAGE_B + 2 * B_TILE_B + sw128((uint32_t)e * 128 + k16 * 16);
    *reinterpret_cast<uint4*>(g_wimg + off) = make_uint4(o[0], o[1], o[2], o[3]);
}

// ---------------- Kernel 1: staged warp-specialized TS GEMM + softmax stats ----------------
__global__ __launch_bounds__(THREADS1, 2)
void k1_gemm(const float* __restrict__ x,
             const float* __restrict__ w,
             const float* __restrict__ bias) {
#if HAS_TCGEN05
    extern __shared__ char sm[];
    const uint32_t smem_base = smem_u32(sm);
    const uint32_t mb_sf0  = smem_base + 16;   // stage0 full: 8 conv warps + 1 B expect_tx
    const uint32_t mb_sf1  = smem_base + 24;
    const uint32_t mb_e0   = smem_base + 32;   // empty (MMA commit)
    const uint32_t mb_e1   = smem_base + 40;
    const uint32_t mb_xf0  = smem_base + 48;   // xs stage full (4 stager warps)
    const uint32_t mb_xf1  = smem_base + 56;
    const uint32_t mb_xr0  = smem_base + 64;   // xs stage free (8 converter warps)
    const uint32_t mb_xr1  = smem_base + 72;
    float* bias_s = reinterpret_cast<float*>(sm + 128);
    const uint32_t b0_abs = (smem_base + 1024 + 1023) & ~1023u;
    const uint32_t xs_abs = b0_abs + B_STAGE_B;            // stays 1024-aligned
    char* xs_ptr = sm + (xs_abs - smem_base);

    const int tid = threadIdx.x;
    const int wid = tid >> 5, lid = tid & 31;
    const long rowbase = (long)blockIdx.x * TILE_M;

    if (wid == 12) {
        T5_ALLOC(smem_base, TMEM_COLS);
        T5_RELINQ();
    }
    if (tid == 0) {
        mbar_init(mb_sf0, 9);   mbar_init(mb_sf1, 9);
        mbar_init(mb_e0, 1);    mbar_init(mb_e1, 1);
        mbar_init(mb_xf0, 4);   mbar_init(mb_xf1, 4);
        mbar_init(mb_xr0, 8);   mbar_init(mb_xr1, 8);
    }
    if (tid < EE) bias_s[tid] = bias[tid];
    __syncthreads();
    const uint32_t tmem = *reinterpret_cast<uint32_t*>(sm);

    if (wid < 8) {
        // ===== converters: LDS from xs -> 3x bf16 -> TMEM =====
        const int awid  = wid & 3;              // subpartition
        const int khalf = wid >> 2;
        const int row   = awid * 32 + lid;
        const uint32_t woff = (uint32_t)awid << 21;
        const uint32_t ccol = (uint32_t)khalf * 16;
        // conflict-free LDS: bank16 = k16 ^ (row&7)
        const char* xrow = xs_ptr + khalf * XS_TILE_B + row * 128;
        const uint32_t rsw = (uint32_t)(row & 7) << 4;

        int xph[2] = {0, 0};
        int eph[2] = {1, 1};
        for (int c = 0; c < NCH; c++) {
            const int s = c & 1;
            mbar_wait(s ? mb_xf1 : mb_xf0, xph[s]); xph[s] ^= 1;

            const char* xb = xrow + s * XS_STAGE_B;
            float4 f4[8];
#pragma unroll
            for (int i = 0; i < 8; i++)
                f4[i] = *reinterpret_cast<const float4*>(xb + (((uint32_t)i << 4) ^ rsw));

            // TMEM A stage free (commit of chunk c-2); hoisted to cap regs
            mbar_wait(s ? mb_e1 : mb_e0, eph[s]); eph[s] ^= 1;

            const uint32_t acol = tmem + TM_A + s * 96 + woff + ccol;
#pragma unroll
            for (int g = 0; g < 2; g++) {
                uint32_t h8[8], m8[8], l8[8];
#pragma unroll
                for (int i = 0; i < 4; i++) {
                    float4 v = f4[g * 4 + i];
#pragma unroll
                    for (int p = 0; p < 2; p++) {
                        float a0 = p ? v.z : v.x;
                        float a1 = p ? v.w : v.y;
                        __nv_bfloat162 H = __float22bfloat162_rn(make_float2(a0, a1));
                        float2 Hf = __bfloat1622float2(H);
                        float r0 = a0 - Hf.x, r1 = a1 - Hf.y;
                        __nv_bfloat162 M = __float22bfloat162_rn(make_float2(r0, r1));
                        float2 Mf = __bfloat1622float2(M);
                        __nv_bfloat162 L = __float22bfloat162_rn(make_float2(r0 - Mf.x, r1 - Mf.y));
                        h8[i * 2 + p] = *reinterpret_cast<uint32_t*>(&H);
                        m8[i * 2 + p] = *reinterpret_cast<uint32_t*>(&M);
                        l8[i * 2 + p] = *reinterpret_cast<uint32_t*>(&L);
                    }
                }
                STTM8(acol + 0 * 32 + g * 8, h8);
                STTM8(acol + 1 * 32 + g * 8, m8);
                STTM8(acol + 2 * 32 + g * 8, l8);
            }
            // all lanes consumed f4 (regs final) -> one elected arrive frees xs
            __syncwarp();
            if (elect1()) mbar_arrive(s ? mb_xr1 : mb_xr0);

            T5_WAIT_ST();            // warp-converged after this
            T5_FENCE_BEFORE();
            if (elect1()) mbar_arrive(s ? mb_sf1 : mb_sf0);
        }

        // ===== epilogue (warps 0-3): wait final commit, read D, softmax =====
        if (wid < 4) {
            mbar_wait(mb_e1, 1);
            T5_FENCE_AFTER();

            float vals[EE];
            {
                uint32_t a[32];
                LDTM32(a, tmem + TM_D);
                T5_WAIT_LD();
#pragma unroll
                for (int e = 0; e < 32; e++)
                    vals[e] = __uint_as_float(a[e]) + bias_s[e];
                LDTM32(a, tmem + TM_D + 32);
                T5_WAIT_LD();
#pragma unroll
                for (int e = 0; e < 32; e++)
                    vals[32 + e] = __uint_as_float(a[e]) + bias_s[32 + e];
            }
            T5_FENCE_BEFORE();

            float bv = vals[0];
            int be = 0;
#pragma unroll
            for (int e = 1; e < EE; e++)
                if (vals[e] > bv) { bv = vals[e]; be = e; }
            float s = 0.f;
#pragma unroll
            for (int e = 0; e < EE; e++)
                s += __expf(vals[e] - bv);

            long r = rowbase + wid * 32 + lid;
            g_p0[r]  = __expf(vals[0] - bv) / s;
            g_idx[r] = be;
        }
    } else if (wid < 12) {
        // ===== x stagers: coalesced LDG.128 -> swizzled STS into xs ring =====
        const int st   = tid - 256;          // 0..127
        const int f16  = st & 15;            // float4 column within chunk
        const int kh   = f16 >> 3;
        const int rb   = st >> 4;            // row offset 0..7
        const float4* xg4 = reinterpret_cast<const float4*>(x) + (size_t)rowbase * 128;
        char* dbase = xs_ptr + kh * XS_TILE_B;
        const uint32_t swc = (uint32_t)(((f16 & 7) ^ rb) << 4);

        int rph[2] = {1, 1};
        for (int c = 0; c < NCH; c++) {
            const int s = c & 1;
            // prefetch first half before waiting (DRAM latency under the wait)
            float4 buf[8];
#pragma unroll
            for (int j = 0; j < 8; j++)
                buf[j] = xg4[(size_t)(j * 8 + rb) * 128 + c * 16 + f16];

            mbar_wait(s ? mb_xr1 : mb_xr0, rph[s]); rph[s] ^= 1;

            char* d = dbase + s * XS_STAGE_B + swc;
#pragma unroll
            for (int j = 0; j < 8; j++)
                *reinterpret_cast<float4*>(d + (size_t)(j * 8 + rb) * 128) = buf[j];
#pragma unroll
            for (int j = 8; j < 16; j++) {
                float4 v = xg4[(size_t)(j * 8 + rb) * 128 + c * 16 + f16];
                *reinterpret_cast<float4*>(d + (size_t)(j * 8 + rb) * 128) = v;
            }
            // warp-wide STS ordering, then one elected arrive publishes the stage
            __syncwarp();
            if (elect1()) mbar_arrive(s ? mb_xf1 : mb_xf0);
        }
    } else {
        // ===== ctrl warp (wid 12): B bulk TMA + MMA =====
        if (elect1()) {
            int ephB[2] = {0, 0};
            int sph[2]  = {0, 0};
            const int ta[6] = {0, 0, 1, 1, 0, 2};
            const int tb[6] = {0, 1, 0, 1, 2, 0};
            uint64_t bd[3];
#pragma unroll
            for (int t = 0; t < 3; t++)
                bd[t] = make_desc_sw128(b0_abs + t * B_TILE_B);

            for (int c = 0; c < NCH; c++) {
                const int s = c & 1;
                if (c >= 1) {  // B buffer free once MMA(c-1) committed
                    const int sp = (c - 1) & 1;
                    mbar_wait(sp ? mb_e1 : mb_e0, ephB[sp]); ephB[sp] ^= 1;
                }
                arrive_expect_tx(s ? mb_sf1 : mb_sf0, B_STAGE_B);
                bulk_g2s(b0_abs, g_wimg + c * B_STAGE_B, B_STAGE_B,
                         s ? mb_sf1 : mb_sf0);

                mbar_wait(s ? mb_sf1 : mb_sf0, sph[s]); sph[s] ^= 1;
                T5_FENCE_AFTER();

                const uint32_t abase = tmem + TM_A + s * 96;
#pragma unroll
                for (int ks = 0; ks < 4; ks++) {
#pragma unroll
                    for (int t = 0; t < 6; t++) {
                        uint32_t a = abase + ta[t] * 32 + ks * 8;
                        uint64_t b = bd[tb[t]] + ks * 2;
                        uint32_t en = !(c == 0 && ks == 0 && t == 0);
                        mma_ts_f16(tmem + TM_D, a, b, IDESC, en);
                    }
                }
                t5_commit(s ? mb_e1 : mb_e0);
            }
        }
    }

    __syncthreads();
    if (wid == 12) {
        T5_DEALLOC(tmem, TMEM_COLS);
    }
#else
    // ---------------- portable fallback (generic-PTX compile phase only) ----------------
    const int tid = threadIdx.x;
    const long rowbase = (long)blockIdx.x * TILE_M;
    if (tid < TILE_M) {
        const float* xr = x + (rowbase + tid) * (size_t)DD;
        float bv = -1e30f;
        int be = 0;
        float vals[EE];
        for (int e = 0; e < EE; e++) {
            float acc = 0.f;
            const float* wr = w + (size_t)e * DD;
            for (int k = 0; k < DD; k++) acc = fmaf(xr[k], wr[k], acc);
            acc += bias[e];
            vals[e] = acc;
            if (acc > bv) { bv = acc; be = e; }
        }
        float s = 0.f;
        for (int e = 0; e < EE; e++) s += __expf(vals[e] - bv);
        long r = rowbase + tid;
        g_p0[r]  = __expf(vals[0] - bv) / s;
        g_idx[r] = be;
    }
#endif
}

// ---------------- Kernel 2: per-batch membership mask -> masked p0 ----------------
__global__ void k2_mask(void) {
    int b    = blockIdx.x * 8 + (threadIdx.x >> 5);
    int lane = threadIdx.x & 31;
    long base = (long)b * NN;
    unsigned long long m = 0ull;
#pragma unroll
    for (int q = 0; q < 4; q++) {
        int v = g_idx[base + lane + 32 * q];
        m |= 1ull << v;
    }
#pragma unroll
    for (int off = 16; off >= 1; off >>= 1)
        m |= __shfl_xor_sync(0xffffffffu, m, off);
#pragma unroll
    for (int h = 0; h < 2; h++) {
        int n = lane + 32 * h;
        g_masked[b * EE + n] = ((m >> n) & 1ull) ? g_p0[base + n] : 0.f;
    }
}

// ---------------- Kernel 3: deterministic column sums (denom, load) ----------------
__global__ void k3_denom(void) {
    __shared__ float sv[256];
    __shared__ int   sc[256];
    int n = blockIdx.x;
    int t = threadIdx.x;
    float s = 0.f;
    int cnt = 0;
    for (int k = 0; k < BB / 256; k++) {
        float v = g_masked[(size_t)(t + k * 256) * EE + n];
        s += v;
        cnt += (v > 0.f);
    }
    sv[t] = s; sc[t] = cnt;
    __syncthreads();
    for (int off = 128; off >= 1; off >>= 1) {
        if (t < off) { sv[t] += sv[t + off]; sc[t] += sc[t + off]; }
        __syncthreads();
    }
    if (t == 0) {
        g_denom[n] = sv[0] + EPS;
        g_load[n]  = sc[0];
    }
}

// ---------------- Kernel 4 (sparse): write only the nonzero gs entries ----------------
__global__ void k4_sparse(float* __restrict__ out) {
    int i = blockIdx.x * blockDim.x + threadIdx.x;   // 0..131071
    int b = i >> 6;
    int n = i & 63;
    float m = g_masked[b * EE + n];
    out[((size_t)b * NN + n) * EE] = m * (CAPACITY / g_denom[n]);
}

// ---------------- Kernel 5: loss ----------------
__global__ void k5_loss(float* __restrict__ lossptr) {
    double si = 0.0, si2 = 0.0, sl = 0.0, sl2 = 0.0;
    for (int n = 0; n < EE; n++) {
        double dn = (double)g_denom[n];
        double S  = dn - (double)EPS;
        double imp = (double)CAPACITY * S / dn;
        si  += imp;
        si2 += imp * imp;
        double ld = (double)g_load[n];
        sl  += ld;
        sl2 += ld * ld;
    }
    const double M = (double)(NN * EE);
    double mean_i = si / M;
    double var_i  = (si2 - si * si / M) / (M - 1.0);
    double cv_i   = var_i / (mean_i * mean_i + 1e-10);
    double mean_l = sl / M;
    double var_l  = (sl2 - sl * sl / M) / (M - 1.0);
    double cv_l   = var_l / (mean_l * mean_l + 1e-10);
    *lossptr = (float)(cv_i + cv_l);
}

extern "C" void kernel_launch(void* const* d_in, const int* in_sizes, int n_in,
                              void* d_out, int out_size) {
    const float* x    = (const float*)d_in[0];
    const float* w    = (const float*)d_in[1];
    const float* bias = (const float*)d_in[2];
    float* out = (float*)d_out;

    cudaFuncSetAttribute(k1_gemm, cudaFuncAttributeMaxDynamicSharedMemorySize, SMEM_TC);

    // 3 image-builder launches first so k1 is the 4th kernel launch (ncu slot)
    k0h<<<16, 256>>>(w);
    k0m<<<16, 256>>>(w);
    k0l<<<16, 256>>>(w);
    k1_gemm<<<ROWS / TILE_M, THREADS1, SMEM_TC>>>(x, w, bias);
    k2_mask<<<BB / 8, 256>>>();
    k3_denom<<<EE, 256>>>();

    const long total = (long)BB * NN * EE;        // 16777216
    if ((long)out_size >= total) {
        cudaMemsetAsync(out, 0, total * sizeof(float));
        k4_sparse<<<(BB * EE) / 256, 256>>>(out);
    }
    if ((long)out_size > total) {
        k5_loss<<<1, 1>>>(out + total);
    } else if ((long)out_size < total) {
        k5_loss<<<1, 1>>>(out);
    }
}

// round 11
// speedup vs baseline: 1.0632x; 1.0632x over previous
#include <cuda_runtime.h>
#include <cuda_bf16.h>
#include <cstdint>

// Problem constants
#define BB 2048
#define NN 128
#define DD 512
#define EE 64
#define ROWS (BB*NN)            // 262144
#define EPS 1e-6f
#define CAPACITY 2048.0f

#define TILE_M 128
#define THREADS1 416            // 13 warps: 8 convert, 4 x-stage, 1 ctrl (B + MMA)

// ---- tiling: A/x chunks of 32 k (16 chunks), B chunks of 64 k (8 chunks) ----
#define ACH 16
#define BCH 8
#define B_TILE_B (EE*128)       // 8192 per term (64-k B chunk)
#define B_STAGE_B (3*B_TILE_B)  // 24576
#define XS_TILE_B (TILE_M*128)  // 16384 (128 rows x 32 floats)
#define SMEM_TC (2048 + 2*B_STAGE_B + 3*XS_TILE_B)   // ~100KB

// TMEM columns: D=0..63, A ring at 64: 4 stages x 48 cols (3 terms x 16)
#define TM_D 0
#define TM_A 64
#define TMEM_COLS 256

// idesc: dtype=F32, atype=BF16, btype=BF16, N=64, M=128, K-major both
#define IDESC ((1u<<4)|(1u<<7)|(1u<<10)|((EE/8)<<17)|((TILE_M/16)<<24))

// Scratch (device globals; no allocation allowed)
__device__ float g_p0[ROWS];
__device__ int   g_idx[ROWS];
__device__ float g_masked[BB*EE];
__device__ float g_denom[EE];
__device__ int   g_load[EE];
// chunk-major pre-swizzled B image: [BCH][3 terms][64 rows x 128B swizzled]
__device__ __align__(128) char g_wimg[BCH * 3 * B_TILE_B];

#define HAS_TCGEN05 (defined(__CUDA_ARCH_FEAT_SM103_ALL) || defined(__CUDA_ARCH_FEAT_SM100_ALL) || defined(__CUDA_ARCH_FEAT_SM101_ALL))

// ---------------- generic helpers ----------------
__device__ __forceinline__ uint32_t sw128(uint32_t o) { return o ^ ((o >> 3) & 0x70); }

__device__ __forceinline__ uint32_t pack_bf2(__nv_bfloat16 a, __nv_bfloat16 b) {
    __nv_bfloat162 t = __halves2bfloat162(a, b);
    return *reinterpret_cast<uint32_t*>(&t);
}

#if HAS_TCGEN05
// ---------------- tcgen05 / TMA PTX helpers (arch-specific target only) ----------------
__device__ __forceinline__ uint32_t smem_u32(const void* p) {
    uint32_t a;
    asm("{ .reg .u64 t; cvta.to.shared.u64 t, %1; cvt.u32.u64 %0, t; }"
        : "=r"(a) : "l"(p));
    return a;
}
__device__ __forceinline__ uint32_t elect1() {
    uint32_t r;
    asm volatile("{\n\t.reg .pred p;\n\telect.sync _|p, 0xFFFFFFFF;\n\t"
                 "selp.b32 %0, 1, 0, p;\n\t}" : "=r"(r));
    return r;
}
__device__ __forceinline__ uint64_t make_desc_sw128(uint32_t addr) {
    const uint64_t base = (2ull << 61) | (1ull << 46) | (64ull << 32) | (1ull << 16);
    return base | ((uint64_t)(addr >> 4) & 0x3FFF);
}
// TS-mode MMA: A in TMEM, B via SMEM descriptor
__device__ __forceinline__ void mma_ts_f16(uint32_t d, uint32_t a, uint64_t b,
                                           uint32_t idesc, uint32_t en) {
    asm volatile(
        "{\n\t.reg .pred p;\n\tsetp.ne.u32 p, %4, 0;\n\t"
        "tcgen05.mma.cta_group::1.kind::f16 [%0], [%1], %2, %3, {%5,%5,%5,%5}, p;\n\t}"
        :: "r"(d), "r"(a), "l"(b), "r"(idesc), "r"(en), "r"(0u) : "memory");
}
__device__ __forceinline__ void mbar_init(uint32_t a, uint32_t cnt) {
    asm volatile("mbarrier.init.shared.b64 [%0], %1;" :: "r"(a), "r"(cnt) : "memory");
}
__device__ __forceinline__ void mbar_arrive(uint32_t a) {
    asm volatile("mbarrier.arrive.release.cta.shared.b64 _, [%0];" :: "r"(a) : "memory");
}
__device__ __forceinline__ void arrive_expect_tx(uint32_t a, uint32_t bytes) {
    asm volatile("mbarrier.arrive.expect_tx.shared.b64 _, [%0], %1;"
                 :: "r"(a), "r"(bytes) : "memory");
}
__device__ __forceinline__ void bulk_g2s(uint32_t dst, const void* src,
                                         uint32_t bytes, uint32_t mbar) {
    asm volatile("cp.async.bulk.shared::cta.global.mbarrier::complete_tx::bytes "
                 "[%0], [%1], %2, [%3];"
                 :: "r"(dst), "l"(src), "r"(bytes), "r"(mbar) : "memory");
}
__device__ __forceinline__ void mbar_wait(uint32_t a, uint32_t parity) {
    uint32_t done;
    asm volatile("{\n\t.reg .pred p;\n\t"
        "mbarrier.try_wait.parity.acquire.cta.shared::cta.b64 p, [%1], %2;\n\t"
        "selp.b32 %0, 1, 0, p;\n\t}" : "=r"(done) : "r"(a), "r"(parity) : "memory");
    while (!done) {
        asm volatile("{\n\t.reg .pred p;\n\t"
            "mbarrier.try_wait.parity.acquire.cta.shared::cta.b64 p, [%1], %2, 0x989680;\n\t"
            "selp.b32 %0, 1, 0, p;\n\t}" : "=r"(done) : "r"(a), "r"(parity) : "memory");
    }
}
__device__ __forceinline__ void t5_commit(uint32_t mb) {
    asm volatile("tcgen05.commit.cta_group::1.mbarrier::arrive::one.shared::cluster.b64 [%0];"
                 :: "r"(mb) : "memory");
}
#define T5_ALLOC(smaddr, n) \
    asm volatile("tcgen05.alloc.cta_group::1.sync.aligned.shared::cta.b32 [%0], %1;" \
                 :: "r"(smaddr), "r"((uint32_t)(n)) : "memory")
#define T5_RELINQ() \
    asm volatile("tcgen05.relinquish_alloc_permit.cta_group::1.sync.aligned;")
#define T5_DEALLOC(t, n) \
    asm volatile("tcgen05.dealloc.cta_group::1.sync.aligned.b32 %0, %1;" :: "r"(t), "r"((uint32_t)(n)))
#define T5_FENCE_AFTER()  asm volatile("tcgen05.fence::after_thread_sync;" ::: "memory")
#define T5_FENCE_BEFORE() asm volatile("tcgen05.fence::before_thread_sync;" ::: "memory")
#define T5_WAIT_LD()      asm volatile("tcgen05.wait::ld.sync.aligned;" ::: "memory")
#define T5_WAIT_ST()      asm volatile("tcgen05.wait::st.sync.aligned;" ::: "memory")

#define STTM8(addr, r) \
    asm volatile("tcgen05.st.sync.aligned.32x32b.x8.b32 [%0], " \
        "{%1,%2,%3,%4,%5,%6,%7,%8};" \
        :: "r"(addr), "r"((r)[0]), "r"((r)[1]), "r"((r)[2]), "r"((r)[3]), \
           "r"((r)[4]), "r"((r)[5]), "r"((r)[6]), "r"((r)[7]) : "memory")

#define LDTM32(r, addr) \
    asm volatile( \
        "tcgen05.ld.sync.aligned.32x32b.x32.b32 " \
        "{%0, %1, %2, %3, %4, %5, %6, %7, " \
        " %8, %9, %10, %11, %12, %13, %14, %15, " \
        " %16, %17, %18, %19, %20, %21, %22, %23, " \
        " %24, %25, %26, %27, %28, %29, %30, %31}, [%32];" \
        : "=r"((r)[0]),  "=r"((r)[1]),  "=r"((r)[2]),  "=r"((r)[3]), \
          "=r"((r)[4]),  "=r"((r)[5]),  "=r"((r)[6]),  "=r"((r)[7]), \
          "=r"((r)[8]),  "=r"((r)[9]),  "=r"((r)[10]), "=r"((r)[11]), \
          "=r"((r)[12]), "=r"((r)[13]), "=r"((r)[14]), "=r"((r)[15]), \
          "=r"((r)[16]), "=r"((r)[17]), "=r"((r)[18]), "=r"((r)[19]), \
          "=r"((r)[20]), "=r"((r)[21]), "=r"((r)[22]), "=r"((r)[23]), \
          "=r"((r)[24]), "=r"((r)[25]), "=r"((r)[26]), "=r"((r)[27]), \
          "=r"((r)[28]), "=r"((r)[29]), "=r"((r)[30]), "=r"((r)[31]) \
        : "r"(addr))
#endif  // HAS_TCGEN05

// ---------------- Kernel 0: build pre-swizzled chunk-major W images ----------------
__global__ void k0h(const float* __restrict__ w) {
    int i = blockIdx.x * blockDim.x + threadIdx.x;      // 0..4095
    int c = i >> 9, e = (i >> 3) & 63, k16 = i & 7;
    const float4* src = reinterpret_cast<const float4*>(w + (size_t)e * DD + c * 64 + k16 * 8);
    float4 a = src[0], b = src[1];
    uint32_t o[4];
    o[0] = pack_bf2(__float2bfloat16(a.x), __float2bfloat16(a.y));
    o[1] = pack_bf2(__float2bfloat16(a.z), __float2bfloat16(a.w));
    o[2] = pack_bf2(__float2bfloat16(b.x), __float2bfloat16(b.y));
    o[3] = pack_bf2(__float2bfloat16(b.z), __float2bfloat16(b.w));
    uint32_t off = c * B_STAGE_B + 0 * B_TILE_B + sw128((uint32_t)e * 128 + k16 * 16);
    *reinterpret_cast<uint4*>(g_wimg + off) = make_uint4(o[0], o[1], o[2], o[3]);
}
__device__ __forceinline__ float bf_res1(float v) {
    return v - __bfloat162float(__float2bfloat16(v));
}
__global__ void k0m(const float* __restrict__ w) {
    int i = blockIdx.x * blockDim.x + threadIdx.x;
    int c = i >> 9, e = (i >> 3) & 63, k16 = i & 7;
    const float4* src = reinterpret_cast<const float4*>(w + (size_t)e * DD + c * 64 + k16 * 8);
    float4 a = src[0], b = src[1];
    float f[8] = {a.x, a.y, a.z, a.w, b.x, b.y, b.z, b.w};
    uint32_t o[4];
#pragma unroll
    for (int q = 0; q < 4; q++)
        o[q] = pack_bf2(__float2bfloat16(bf_res1(f[q*2])), __float2bfloat16(bf_res1(f[q*2+1])));
    uint32_t off = c * B_STAGE_B + 1 * B_TILE_B + sw128((uint32_t)e * 128 + k16 * 16);
    *reinterpret_cast<uint4*>(g_wimg + off) = make_uint4(o[0], o[1], o[2], o[3]);
}
__global__ void k0l(const float* __restrict__ w) {
    int i = blockIdx.x * blockDim.x + threadIdx.x;
    int c = i >> 9, e = (i >> 3) & 63, k16 = i & 7;
    const float4* src = reinterpret_cast<const float4*>(w + (size_t)e * DD + c * 64 + k16 * 8);
    float4 a = src[0], b = src[1];
    float f[8] = {a.x, a.y, a.z, a.w, b.x, b.y, b.z, b.w};
    uint32_t o[4];
#pragma unroll
    for (int q = 0; q < 4; q++) {
        float r0 = bf_res1(f[q*2]),   l0 = bf_res1(r0);
        float r1 = bf_res1(f[q*2+1]), l1 = bf_res1(r1);
        o[q] = pack_bf2(__float2bfloat16(l0), __float2bfloat16(l1));
    }
    uint32_t off = c * B_STAGE_B + 2 * B_TILE_B + sw128((uint32_t)e * 128 + k16 * 16);
    *reinterpret_cast<uint4*>(g_wimg + off) = make_uint4(o[0], o[1], o[2], o[3]);
}

// ---------------- Kernel 1: deep-pipelined warp-specialized TS GEMM ----------------
__global__ __launch_bounds__(THREADS1, 2)
void k1_gemm(const float* __restrict__ x,
             const float* __restrict__ w,
             const float* __restrict__ bias) {
#if HAS_TCGEN05
    extern __shared__ char sm[];
    const uint32_t smem_base = smem_u32(sm);
    // barriers: sf[4] A-stage full (8 arrivals), e[4] A-stage empty (commit),
    //           bf[2] B full (expect_tx), xf[3] xs full (4), xr[3] xs free (8)
#define MB_SF(i) (smem_base + 16  + (uint32_t)(i)*8)
#define MB_E(i)  (smem_base + 48  + (uint32_t)(i)*8)
#define MB_BF(i) (smem_base + 80  + (uint32_t)(i)*8)
#define MB_XF(i) (smem_base + 96  + (uint32_t)(i)*8)
#define MB_XR(i) (smem_base + 120 + (uint32_t)(i)*8)
    float* bias_s = reinterpret_cast<float*>(sm + 256);
    const uint32_t b0_abs = (smem_base + 1024 + 1023) & ~1023u;
    const uint32_t xs_abs = b0_abs + 2 * B_STAGE_B;
    char* xs_ptr = sm + (xs_abs - smem_base);

    const int tid = threadIdx.x;
    const int wid = tid >> 5, lid = tid & 31;
    const long rowbase = (long)blockIdx.x * TILE_M;

    if (wid == 12) {
        T5_ALLOC(smem_base, TMEM_COLS);
        T5_RELINQ();
    }
    if (tid == 0) {
#pragma unroll
        for (int i = 0; i < 4; i++) { mbar_init(MB_SF(i), 8); mbar_init(MB_E(i), 1); }
        mbar_init(MB_BF(0), 1); mbar_init(MB_BF(1), 1);
#pragma unroll
        for (int i = 0; i < 3; i++) { mbar_init(MB_XF(i), 4); mbar_init(MB_XR(i), 8); }
    }
    if (tid < EE) bias_s[tid] = bias[tid];
    __syncthreads();
    const uint32_t tmem = *reinterpret_cast<uint32_t*>(sm);

    if (wid < 8) {
        // ===== converters: LDS from xs -> 3x bf16 -> TMEM (A ring 4-deep) =====
        const int awid = wid & 3;               // subpartition
        const int kh   = wid >> 2;              // 16-k half of the 32-k chunk
        const int row  = awid * 32 + lid;
        const uint32_t woff = (uint32_t)awid << 21;
        const char* xrow = xs_ptr + row * 128;
        const uint32_t rsw = (uint32_t)(row & 7);

        uint32_t xmask = 0;        // xf parities per xs stage (init 0)
        uint32_t emask = 0xF;      // e parities per A stage (init 1)
        int sx = 0;
        for (int c = 0; c < ACH; c++) {
            const int s = c & 3;
            mbar_wait(MB_XF(sx), (xmask >> sx) & 1); xmask ^= 1u << sx;

            const char* xb = xrow + sx * XS_TILE_B;
            float4 f4[4];
#pragma unroll
            for (int i = 0; i < 4; i++)
                f4[i] = *reinterpret_cast<const float4*>(
                    xb + (((uint32_t)(kh * 4 + i) ^ rsw) << 4));

            // convert fully BEFORE the e-wait (off the critical section)
            uint32_t o0[8], o1[8], o2[8];
#pragma unroll
            for (int i = 0; i < 4; i++) {
                float4 v = f4[i];
#pragma unroll
                for (int p = 0; p < 2; p++) {
                    float a0 = p ? v.z : v.x;
                    float a1 = p ? v.w : v.y;
                    __nv_bfloat162 H = __float22bfloat162_rn(make_float2(a0, a1));
                    float2 Hf = __bfloat1622float2(H);
                    float r0 = a0 - Hf.x, r1 = a1 - Hf.y;
                    __nv_bfloat162 M = __float22bfloat162_rn(make_float2(r0, r1));
                    float2 Mf = __bfloat1622float2(M);
                    __nv_bfloat162 L = __float22bfloat162_rn(make_float2(r0 - Mf.x, r1 - Mf.y));
                    o0[i * 2 + p] = *reinterpret_cast<uint32_t*>(&H);
                    o1[i * 2 + p] = *reinterpret_cast<uint32_t*>(&M);
                    o2[i * 2 + p] = *reinterpret_cast<uint32_t*>(&L);
                }
            }
            __syncwarp();
            if (elect1()) mbar_arrive(MB_XR(sx));          // xs stage free early
            sx = (sx == 2) ? 0 : sx + 1;

            mbar_wait(MB_E(s), (emask >> s) & 1); emask ^= 1u << s;   // A stage free
            const uint32_t acol = tmem + TM_A + s * 48 + woff + kh * 8;
            STTM8(acol + 0,  o0);
            STTM8(acol + 16, o1);
            STTM8(acol + 32, o2);
            T5_WAIT_ST();
            T5_FENCE_BEFORE();
            if (elect1()) mbar_arrive(MB_SF(s));
        }

        // ===== epilogue (warps 0-3): wait 4th commit on e[3], read D, softmax =====
        if (wid < 4) {
            mbar_wait(MB_E(3), 1);
            T5_FENCE_AFTER();

            float vals[EE];
            {
                uint32_t a[32];
                LDTM32(a, tmem + TM_D);
                T5_WAIT_LD();
#pragma unroll
                for (int e = 0; e < 32; e++)
                    vals[e] = __uint_as_float(a[e]) + bias_s[e];
                LDTM32(a, tmem + TM_D + 32);
                T5_WAIT_LD();
#pragma unroll
                for (int e = 0; e < 32; e++)
                    vals[32 + e] = __uint_as_float(a[e]) + bias_s[32 + e];
            }
            T5_FENCE_BEFORE();

            float bv = vals[0];
            int be = 0;
#pragma unroll
            for (int e = 1; e < EE; e++)
                if (vals[e] > bv) { bv = vals[e]; be = e; }
            float s = 0.f;
#pragma unroll
            for (int e = 0; e < EE; e++)
                s += __expf(vals[e] - bv);

            long r = rowbase + wid * 32 + lid;
            g_p0[r]  = __expf(vals[0] - bv) / s;
            g_idx[r] = be;
        }
    } else if (wid < 12) {
        // ===== x stagers: coalesced LDG.128 -> swizzled STS into 3-deep xs ring =====
        const int st  = tid - 256;           // 0..127
        const int f16 = st & 7;              // f4 column (0-7) within 32-k chunk
        const int rb  = st >> 3;             // row 0..15 (rows rb, rb+16, ...)
        const float4* xg4 = reinterpret_cast<const float4*>(x) + (size_t)rowbase * 128;
        const uint32_t swc = (uint32_t)((f16 ^ (rb & 7)) << 4);

        uint32_t rmask = 0x7;                // xr parities (init 1)
        int sx = 0;
        for (int c = 0; c < ACH; c++) {
            float4 buf[8];
#pragma unroll
            for (int j = 0; j < 8; j++)
                buf[j] = xg4[(size_t)(rb + j * 16) * 128 + c * 8 + f16];

            mbar_wait(MB_XR(sx), (rmask >> sx) & 1); rmask ^= 1u << sx;

            char* d = xs_ptr + sx * XS_TILE_B + swc;
#pragma unroll
            for (int j = 0; j < 8; j++)
                *reinterpret_cast<float4*>(d + (size_t)(rb + j * 16) * 128) = buf[j];
            __syncwarp();
            if (elect1()) mbar_arrive(MB_XF(sx));
            sx = (sx == 2) ? 0 : sx + 1;
        }
    } else {
        // ===== ctrl warp (wid 12): B double-buffered TMA + MMA =====
        if (elect1()) {
            // pre-issue B chunks 0 and 1
            arrive_expect_tx(MB_BF(0), B_STAGE_B);
            bulk_g2s(b0_abs, g_wimg, B_STAGE_B, MB_BF(0));
            arrive_expect_tx(MB_BF(1), B_STAGE_B);
            bulk_g2s(b0_abs + B_STAGE_B, g_wimg + B_STAGE_B, B_STAGE_B, MB_BF(1));

            uint64_t bd0[3], bd1[3];
#pragma unroll
            for (int t = 0; t < 3; t++) {
                bd0[t] = make_desc_sw128(b0_abs + t * B_TILE_B);
                bd1[t] = make_desc_sw128(b0_abs + B_STAGE_B + t * B_TILE_B);
            }
            const int ta[6] = {0, 0, 1, 1, 0, 2};
            const int tb[6] = {0, 1, 0, 1, 2, 0};

            uint32_t smask = 0;    // sf parities (init 0)
            uint32_t bmask = 0;    // bf parities (init 0)
            uint32_t ebmask = 0;   // e parities for B-prefetch (stages 1,3; init 0)
            for (int c = 0; c < ACH; c++) {
                const int s  = c & 3;
                const int cb = c >> 1;

                mbar_wait(MB_SF(s), (smask >> s) & 1); smask ^= 1u << s;
                if ((c & 1) == 0) {
                    const int bs = cb & 1;
                    mbar_wait(MB_BF(bs), (bmask >> bs) & 1); bmask ^= 1u << bs;
                }
                T5_FENCE_AFTER();

                const uint32_t abase = tmem + TM_A + s * 48;
                const uint64_t* bd = (cb & 1) ? bd1 : bd0;
                const int koff = (c & 1) * 4;
#pragma unroll
                for (int ks = 0; ks < 2; ks++) {
#pragma unroll
                    for (int t = 0; t < 6; t++) {
                        uint32_t a = abase + ta[t] * 16 + ks * 8;
                        uint64_t b = bd[tb[t]] + koff + ks * 2;
                        uint32_t en = !(c == 0 && ks == 0 && t == 0);
                        mma_ts_f16(tmem + TM_D, a, b, IDESC, en);
                    }
                }
                t5_commit(MB_E(s));

                // prefetch next B chunk (2 A-chunks of lead)
                if ((c & 1) == 0 && c + 2 < ACH) {
                    const int cbn = cb + 1;
                    if (cbn >= 2) {
                        const int es = (c - 1) & 3;          // 1 or 3
                        const int ei = (es == 1) ? 0 : 1;
                        mbar_wait(MB_E(es), (ebmask >> ei) & 1); ebmask ^= 1u << ei;
                        arrive_expect_tx(MB_BF(cbn & 1), B_STAGE_B);
                        bulk_g2s(b0_abs + (cbn & 1) * B_STAGE_B,
                                 g_wimg + cbn * B_STAGE_B, B_STAGE_B, MB_BF(cbn & 1));
                    }
                }
            }
        }
    }

    __syncthreads();
    if (wid == 12) {
        T5_DEALLOC(tmem, TMEM_COLS);
    }
#else
    // ---------------- portable fallback (generic-PTX compile phase only) ----------------
    const int tid = threadIdx.x;
    const long rowbase = (long)blockIdx.x * TILE_M;
    if (tid < TILE_M) {
        const float* xr = x + (rowbase + tid) * (size_t)DD;
        float bv = -1e30f;
        int be = 0;
        float vals[EE];
        for (int e = 0; e < EE; e++) {
            float acc = 0.f;
            const float* wr = w + (size_t)e * DD;
            for (int k = 0; k < DD; k++) acc = fmaf(xr[k], wr[k], acc);
            acc += bias[e];
            vals[e] = acc;
            if (acc > bv) { bv = acc; be = e; }
        }
        float s = 0.f;
        for (int e = 0; e < EE; e++) s += __expf(vals[e] - bv);
        long r = rowbase + tid;
        g_p0[r]  = __expf(vals[0] - bv) / s;
        g_idx[r] = be;
    }
#endif
}

// ---------------- Kernel 2: per-batch membership mask -> masked p0 ----------------
__global__ void k2_mask(void) {
    int b    = blockIdx.x * 8 + (threadIdx.x >> 5);
    int lane = threadIdx.x & 31;
    long base = (long)b * NN;
    unsigned long long m = 0ull;
#pragma unroll
    for (int q = 0; q < 4; q++) {
        int v = g_idx[base + lane + 32 * q];
        m |= 1ull << v;
    }
#pragma unroll
    for (int off = 16; off >= 1; off >>= 1)
        m |= __shfl_xor_sync(0xffffffffu, m, off);
#pragma unroll
    for (int h = 0; h < 2; h++) {
        int n = lane + 32 * h;
        g_masked[b * EE + n] = ((m >> n) & 1ull) ? g_p0[base + n] : 0.f;
    }
}

// ---------------- Kernel 3: deterministic column sums (denom, load) ----------------
__global__ void k3_denom(void) {
    __shared__ float sv[256];
    __shared__ int   sc[256];
    int n = blockIdx.x;
    int t = threadIdx.x;
    float s = 0.f;
    int cnt = 0;
    for (int k = 0; k < BB / 256; k++) {
        float v = g_masked[(size_t)(t + k * 256) * EE + n];
        s += v;
        cnt += (v > 0.f);
    }
    sv[t] = s; sc[t] = cnt;
    __syncthreads();
    for (int off = 128; off >= 1; off >>= 1) {
        if (t < off) { sv[t] += sv[t + off]; sc[t] += sc[t + off]; }
        __syncthreads();
    }
    if (t == 0) {
        g_denom[n] = sv[0] + EPS;
        g_load[n]  = sc[0];
    }
}

// ---------------- Kernel 4 (sparse): write only the nonzero gs entries ----------------
__global__ void k4_sparse(float* __restrict__ out) {
    int i = blockIdx.x * blockDim.x + threadIdx.x;   // 0..131071
    int b = i >> 6;
    int n = i & 63;
    float m = g_masked[b * EE + n];
    out[((size_t)b * NN + n) * EE] = m * (CAPACITY / g_denom[n]);
}

// ---------------- Kernel 5: loss ----------------
__global__ void k5_loss(float* __restrict__ lossptr) {
    double si = 0.0, si2 = 0.0, sl = 0.0, sl2 = 0.0;
    for (int n = 0; n < EE; n++) {
        double dn = (double)g_denom[n];
        double S  = dn - (double)EPS;
        double imp = (double)CAPACITY * S / dn;
        si  += imp;
        si2 += imp * imp;
        double ld = (double)g_load[n];
        sl  += ld;
        sl2 += ld * ld;
    }
    const double M = (double)(NN * EE);
    double mean_i = si / M;
    double var_i  = (si2 - si * si / M) / (M - 1.0);
    double cv_i   = var_i / (mean_i * mean_i + 1e-10);
    double mean_l = sl / M;
    double var_l  = (sl2 - sl * sl / M) / (M - 1.0);
    double cv_l   = var_l / (mean_l * mean_l + 1e-10);
    *lossptr = (float)(cv_i + cv_l);
}

extern "C" void kernel_launch(void* const* d_in, const int* in_sizes, int n_in,
                              void* d_out, int out_size) {
    const float* x    = (const float*)d_in[0];
    const float* w    = (const float*)d_in[1];
    const float* bias = (const float*)d_in[2];
    float* out = (float*)d_out;

    cudaFuncSetAttribute(k1_gemm, cudaFuncAttributeMaxDynamicSharedMemorySize, SMEM_TC);

    // 3 image-builder launches first so k1 is the 4th kernel launch (ncu slot)
    k0h<<<16, 256>>>(w);
    k0m<<<16, 256>>>(w);
    k0l<<<16, 256>>>(w);
    k1_gemm<<<ROWS / TILE_M, THREADS1, SMEM_TC>>>(x, w, bias);
    k2_mask<<<BB / 8, 256>>>();
    k3_denom<<<EE, 256>>>();

    const long total = (long)BB * NN * EE;        // 16777216
    if ((long)out_size >= total) {
        cudaMemsetAsync(out, 0, total * sizeof(float));
        k4_sparse<<<(BB * EE) / 256, 256>>>(out);
    }
    if ((long)out_size > total) {
        k5_loss<<<1, 1>>>(out + total);
    } else if ((long)out_size < total) {
        k5_loss<<<1, 1>>>(out);
    }
}